// round 1
// baseline (speedup 1.0000x reference)
#include <cuda_runtime.h>
#include <cuda_bf16.h>
#include <cstdint>

// Problem constants (fixed shapes)
#define B_   32
#define T_   8
#define LL   197
#define CC   768
#define CAd  384
#define BTd  256            // B_*T_
#define MM   50176          // BTd*196

// Scratch (device globals — no allocation allowed)
__device__ __nv_bfloat16 g_h1[(size_t)MM * CAd];
__device__ __nv_bfloat16 g_h2[(size_t)MM * CAd];
__device__ __nv_bfloat16 g_w1[CAd * CC];
__device__ __nv_bfloat16 g_w2[CC * CAd];

// ---------------------------------------------------------------------------
// prep: convert weights to bf16, copy CLS rows of x into out
// ---------------------------------------------------------------------------
__global__ void prep_kernel(const float* __restrict__ W1, const float* __restrict__ W2,
                            const float* __restrict__ x, float* __restrict__ out) {
    int stride = gridDim.x * blockDim.x;
    int i0 = blockIdx.x * blockDim.x + threadIdx.x;
    for (int i = i0; i < CAd * CC; i += stride) g_w1[i] = __float2bfloat16(W1[i]);
    for (int i = i0; i < CAd * CC; i += stride) g_w2[i] = __float2bfloat16(W2[i]);
    for (int i = i0; i < BTd * CC; i += stride) {
        int bt = i / CC, c = i - bt * CC;
        size_t off = (size_t)bt * LL * CC + c;
        out[off] = x[off];
    }
}

// ---------------------------------------------------------------------------
// GEMM helpers (mma.sync m16n8k16 bf16)
// ---------------------------------------------------------------------------
__device__ __forceinline__ uint32_t smem_u32(const void* p) {
    return (uint32_t)__cvta_generic_to_shared(p);
}
__device__ __forceinline__ void ldm_x4(uint32_t* r, uint32_t addr) {
    asm volatile("ldmatrix.sync.aligned.m8n8.x4.shared.b16 {%0,%1,%2,%3}, [%4];\n"
                 : "=r"(r[0]), "=r"(r[1]), "=r"(r[2]), "=r"(r[3]) : "r"(addr));
}
__device__ __forceinline__ void mma_bf16(float* d, const uint32_t* a, uint32_t b0, uint32_t b1) {
    asm volatile(
        "mma.sync.aligned.m16n8k16.row.col.f32.bf16.bf16.f32 "
        "{%0,%1,%2,%3}, {%4,%5,%6,%7}, {%8,%9}, {%0,%1,%2,%3};\n"
        : "+f"(d[0]), "+f"(d[1]), "+f"(d[2]), "+f"(d[3])
        : "r"(a[0]), "r"(a[1]), "r"(a[2]), "r"(a[3]), "r"(b0), "r"(b1));
}

#define SK 40   // smem row stride (32 + 8 pad) -> 80B stride, ldmatrix conflict-free

// ---------------------------------------------------------------------------
// fc1: h1[m, n] = sum_k x[xrow(m), k] * W1[n, k] + b1[n]   (A fp32 -> bf16 on the fly)
// M=50176, N=384, K=768; tile 128x128x32; 8 warps as 4(M)x2(N), warp tile 32x64
// ---------------------------------------------------------------------------
__global__ __launch_bounds__(256) void fc1_kernel(const float* __restrict__ x,
                                                  const float* __restrict__ b1) {
    __shared__ __align__(16) __nv_bfloat16 As[2][128 * SK];
    __shared__ __align__(16) __nv_bfloat16 Bs[2][128 * SK];
    const int tid = threadIdx.x;
    const int bm = blockIdx.y * 128;
    const int bn = blockIdx.x * 128;

    // A loader: 128 rows x 32 cols fp32, float4 per thread, 4 passes of 32 rows
    const int a_row = tid >> 3;
    const int a_col = (tid & 7) * 4;
    const float* aptr[4];
#pragma unroll
    for (int p = 0; p < 4; p++) {
        int m = bm + a_row + p * 32;
        int xr = m + m / 196 + 1;           // skip CLS per bt
        aptr[p] = x + (size_t)xr * CC + a_col;
    }
    // B loader: 128 rows x 32 cols bf16, uint4 per thread, 2 passes of 64 rows
    const int b_row = tid >> 2;
    const int b_col = (tid & 3) * 8;
    const __nv_bfloat16* bptr[2];
#pragma unroll
    for (int p = 0; p < 2; p++) bptr[p] = g_w1 + (size_t)(bn + b_row + p * 64) * CC + b_col;

    const int lane = tid & 31;
    const int warp = tid >> 5;
    const int wm = (warp & 3) * 32;
    const int wn = (warp >> 2) * 64;
    const int lr = ((lane >> 3) & 1) * 8 + (lane & 7);  // ldmatrix row offset
    const int kc = (lane >> 4) * 8;                     // ldmatrix col offset

    float acc[2][8][4];
#pragma unroll
    for (int i = 0; i < 2; i++)
#pragma unroll
        for (int j = 0; j < 8; j++)
#pragma unroll
            for (int c = 0; c < 4; c++) acc[i][j][c] = 0.f;

    float4 av[4];
    uint4 bv[2];
    // preload tile 0
#pragma unroll
    for (int p = 0; p < 4; p++) av[p] = *(const float4*)(aptr[p]);
#pragma unroll
    for (int p = 0; p < 2; p++) bv[p] = *(const uint4*)(bptr[p]);
#pragma unroll
    for (int p = 0; p < 4; p++) {
        __nv_bfloat162 p0 = __floats2bfloat162_rn(av[p].x, av[p].y);
        __nv_bfloat162 p1 = __floats2bfloat162_rn(av[p].z, av[p].w);
        uint2 u; u.x = *(uint32_t*)&p0; u.y = *(uint32_t*)&p1;
        *(uint2*)&As[0][(a_row + p * 32) * SK + a_col] = u;
    }
#pragma unroll
    for (int p = 0; p < 2; p++) *(uint4*)&Bs[0][(b_row + p * 64) * SK + b_col] = bv[p];
    __syncthreads();

    const int nk = CC / 32;  // 24
    for (int kt = 0; kt < nk; kt++) {
        int cur = kt & 1;
        if (kt + 1 < nk) {
            int k0 = (kt + 1) * 32;
#pragma unroll
            for (int p = 0; p < 4; p++) av[p] = *(const float4*)(aptr[p] + k0);
#pragma unroll
            for (int p = 0; p < 2; p++) bv[p] = *(const uint4*)(bptr[p] + k0);
        }
        uint32_t a_s = smem_u32(&As[cur][0]);
        uint32_t b_s = smem_u32(&Bs[cur][0]);
#pragma unroll
        for (int ks = 0; ks < 32; ks += 16) {
            uint32_t ra[2][4], rb[4][4];
#pragma unroll
            for (int i = 0; i < 2; i++)
                ldm_x4(ra[i], a_s + (uint32_t)(((wm + i * 16 + lr) * SK + ks + kc) * 2));
#pragma unroll
            for (int j = 0; j < 4; j++)
                ldm_x4(rb[j], b_s + (uint32_t)(((wn + j * 16 + lr) * SK + ks + kc) * 2));
#pragma unroll
            for (int i = 0; i < 2; i++)
#pragma unroll
                for (int j = 0; j < 4; j++) {
                    mma_bf16(acc[i][2 * j],     ra[i], rb[j][0], rb[j][2]);
                    mma_bf16(acc[i][2 * j + 1], ra[i], rb[j][1], rb[j][3]);
                }
        }
        if (kt + 1 < nk) {
            int nxt = cur ^ 1;
#pragma unroll
            for (int p = 0; p < 4; p++) {
                __nv_bfloat162 p0 = __floats2bfloat162_rn(av[p].x, av[p].y);
                __nv_bfloat162 p1 = __floats2bfloat162_rn(av[p].z, av[p].w);
                uint2 u; u.x = *(uint32_t*)&p0; u.y = *(uint32_t*)&p1;
                *(uint2*)&As[nxt][(a_row + p * 32) * SK + a_col] = u;
            }
#pragma unroll
            for (int p = 0; p < 2; p++)
                *(uint4*)&Bs[nxt][(b_row + p * 64) * SK + b_col] = bv[p];
        }
        __syncthreads();
    }

    // epilogue: +bias, write bf16 pairs to h1
    const int lane4 = lane & 3, laneg = lane >> 2;
    uint32_t* h1w = (uint32_t*)g_h1;
#pragma unroll
    for (int i = 0; i < 2; i++) {
#pragma unroll
        for (int jj = 0; jj < 8; jj++) {
            int n = bn + wn + jj * 8 + lane4 * 2;
            float bx = b1[n], by = b1[n + 1];
            int m0 = bm + wm + i * 16 + laneg;
            __nv_bfloat162 v0 = __floats2bfloat162_rn(acc[i][jj][0] + bx, acc[i][jj][1] + by);
            h1w[(size_t)m0 * (CAd / 2) + (n >> 1)] = *(uint32_t*)&v0;
            __nv_bfloat162 v1 = __floats2bfloat162_rn(acc[i][jj][2] + bx, acc[i][jj][3] + by);
            h1w[(size_t)(m0 + 8) * (CAd / 2) + (n >> 1)] = *(uint32_t*)&v1;
        }
    }
}

// ---------------------------------------------------------------------------
// depthwise 3x3x3 conv: h2 = conv(h1) + conv_b
// block = (channel chunk of 8, batch); smem halo tile [10][16][16][8ch] bf16
// ---------------------------------------------------------------------------
__global__ __launch_bounds__(256) void conv_kernel(const float* __restrict__ cw,
                                                   const float* __restrict__ cb) {
    __shared__ uint32_t tile[10 * 16 * 16 * 4];  // bf16x2 words, 40960 B
    const int tid = threadIdx.x;
    const int cc = blockIdx.x;  // 0..47 (channel chunk of 8)
    const int bb = blockIdx.y;  // 0..31
    const uint32_t* h1w = (const uint32_t*)g_h1;

    for (int idx = tid; idx < 10 * 16 * 16 * 4; idx += 256) {
        int p = idx & 3;
        int sp = idx >> 2;
        int w = sp & 15, h = (sp >> 4) & 15, t = sp >> 8;
        int ts = t - 1, hs = h - 1, ws = w - 1;
        uint32_t v = 0;
        if ((unsigned)ts < 8u && (unsigned)hs < 14u && (unsigned)ws < 14u) {
            int row = (bb * 8 + ts) * 196 + hs * 14 + ws;
            v = h1w[(size_t)row * 192 + cc * 4 + p];
        }
        tile[idx] = v;
    }
    __syncthreads();

    const int p = tid & 3;
    const int c0 = cc * 8 + p * 2;
    float wx[27], wy[27];
#pragma unroll
    for (int i = 0; i < 27; i++) {
        wx[i] = cw[c0 * 27 + i];
        wy[i] = cw[(c0 + 1) * 27 + i];
    }
    const float bx = cb[c0], by = cb[c0 + 1];
    uint32_t* h2w = (uint32_t*)g_h2;

    for (int s = tid >> 2; s < 1568; s += 64) {
        int t = s / 196;
        int rem = s - t * 196;
        int h = rem / 14;
        int w = rem - h * 14;
        float ax = bx, ay = by;
#pragma unroll
        for (int dt = 0; dt < 3; dt++)
#pragma unroll
            for (int dh = 0; dh < 3; dh++)
#pragma unroll
                for (int dw = 0; dw < 3; dw++) {
                    uint32_t v = tile[(((t + dt) * 16 + (h + dh)) * 16 + (w + dw)) * 4 + p];
                    float lo = __uint_as_float(v << 16);
                    float hi = __uint_as_float(v & 0xffff0000u);
                    int wi = dt * 9 + dh * 3 + dw;
                    ax = fmaf(wx[wi], lo, ax);
                    ay = fmaf(wy[wi], hi, ay);
                }
        __nv_bfloat162 r = __floats2bfloat162_rn(ax, ay);
        int row = (bb * 8 + t) * 196 + h * 14 + w;
        h2w[(size_t)row * 192 + cc * 4 + p] = *(uint32_t*)&r;
    }
}

// ---------------------------------------------------------------------------
// fc2: out[xrow(m), n] = sum_a h2[m, a] * W2[n, a] + b2[n] + x[xrow(m), n]
// M=50176, N=768, K=384; pure bf16 A; fused residual epilogue
// ---------------------------------------------------------------------------
__global__ __launch_bounds__(256) void fc2_kernel(const float* __restrict__ x,
                                                  const float* __restrict__ b2,
                                                  float* __restrict__ out) {
    __shared__ __align__(16) __nv_bfloat16 As[2][128 * SK];
    __shared__ __align__(16) __nv_bfloat16 Bs[2][128 * SK];
    const int tid = threadIdx.x;
    const int bm = blockIdx.y * 128;
    const int bn = blockIdx.x * 128;

    const int a_row = tid >> 2;
    const int a_col = (tid & 3) * 8;
    const __nv_bfloat16* aptr[2];
#pragma unroll
    for (int p = 0; p < 2; p++) aptr[p] = g_h2 + (size_t)(bm + a_row + p * 64) * CAd + a_col;
    const __nv_bfloat16* bptr[2];
#pragma unroll
    for (int p = 0; p < 2; p++) bptr[p] = g_w2 + (size_t)(bn + a_row + p * 64) * CAd + a_col;

    const int lane = tid & 31;
    const int warp = tid >> 5;
    const int wm = (warp & 3) * 32;
    const int wn = (warp >> 2) * 64;
    const int lr = ((lane >> 3) & 1) * 8 + (lane & 7);
    const int kc = (lane >> 4) * 8;

    float acc[2][8][4];
#pragma unroll
    for (int i = 0; i < 2; i++)
#pragma unroll
        for (int j = 0; j < 8; j++)
#pragma unroll
            for (int c = 0; c < 4; c++) acc[i][j][c] = 0.f;

    uint4 av[2], bv[2];
#pragma unroll
    for (int p = 0; p < 2; p++) av[p] = *(const uint4*)(aptr[p]);
#pragma unroll
    for (int p = 0; p < 2; p++) bv[p] = *(const uint4*)(bptr[p]);
#pragma unroll
    for (int p = 0; p < 2; p++) *(uint4*)&As[0][(a_row + p * 64) * SK + a_col] = av[p];
#pragma unroll
    for (int p = 0; p < 2; p++) *(uint4*)&Bs[0][(a_row + p * 64) * SK + a_col] = bv[p];
    __syncthreads();

    const int nk = CAd / 32;  // 12
    for (int kt = 0; kt < nk; kt++) {
        int cur = kt & 1;
        if (kt + 1 < nk) {
            int k0 = (kt + 1) * 32;
#pragma unroll
            for (int p = 0; p < 2; p++) av[p] = *(const uint4*)(aptr[p] + k0);
#pragma unroll
            for (int p = 0; p < 2; p++) bv[p] = *(const uint4*)(bptr[p] + k0);
        }
        uint32_t a_s = smem_u32(&As[cur][0]);
        uint32_t b_s = smem_u32(&Bs[cur][0]);
#pragma unroll
        for (int ks = 0; ks < 32; ks += 16) {
            uint32_t ra[2][4], rb[4][4];
#pragma unroll
            for (int i = 0; i < 2; i++)
                ldm_x4(ra[i], a_s + (uint32_t)(((wm + i * 16 + lr) * SK + ks + kc) * 2));
#pragma unroll
            for (int j = 0; j < 4; j++)
                ldm_x4(rb[j], b_s + (uint32_t)(((wn + j * 16 + lr) * SK + ks + kc) * 2));
#pragma unroll
            for (int i = 0; i < 2; i++)
#pragma unroll
                for (int j = 0; j < 4; j++) {
                    mma_bf16(acc[i][2 * j],     ra[i], rb[j][0], rb[j][2]);
                    mma_bf16(acc[i][2 * j + 1], ra[i], rb[j][1], rb[j][3]);
                }
        }
        if (kt + 1 < nk) {
            int nxt = cur ^ 1;
#pragma unroll
            for (int p = 0; p < 2; p++) *(uint4*)&As[nxt][(a_row + p * 64) * SK + a_col] = av[p];
#pragma unroll
            for (int p = 0; p < 2; p++) *(uint4*)&Bs[nxt][(a_row + p * 64) * SK + a_col] = bv[p];
        }
        __syncthreads();
    }

    // epilogue: + bias + residual x, fp32 out
    const int lane4 = lane & 3, laneg = lane >> 2;
#pragma unroll
    for (int i = 0; i < 2; i++) {
#pragma unroll
        for (int jj = 0; jj < 8; jj++) {
            int n = bn + wn + jj * 8 + lane4 * 2;
            float bx = b2[n], by = b2[n + 1];
            int m0 = bm + wm + i * 16 + laneg;
            int xr0 = m0 + m0 / 196 + 1;
            const float2 xv0 = *(const float2*)(x + (size_t)xr0 * CC + n);
            float2 o0;
            o0.x = acc[i][jj][0] + bx + xv0.x;
            o0.y = acc[i][jj][1] + by + xv0.y;
            *(float2*)(out + (size_t)xr0 * CC + n) = o0;
            int m1 = m0 + 8;
            int xr1 = m1 + m1 / 196 + 1;
            const float2 xv1 = *(const float2*)(x + (size_t)xr1 * CC + n);
            float2 o1;
            o1.x = acc[i][jj][2] + bx + xv1.x;
            o1.y = acc[i][jj][3] + by + xv1.y;
            *(float2*)(out + (size_t)xr1 * CC + n) = o1;
        }
    }
}

// ---------------------------------------------------------------------------
extern "C" void kernel_launch(void* const* d_in, const int* in_sizes, int n_in,
                              void* d_out, int out_size) {
    const float* x      = (const float*)d_in[0];
    const float* W1     = (const float*)d_in[1];
    const float* b1     = (const float*)d_in[2];
    const float* conv_w = (const float*)d_in[3];
    const float* conv_b = (const float*)d_in[4];
    const float* W2     = (const float*)d_in[5];
    const float* b2     = (const float*)d_in[6];
    float* out = (float*)d_out;

    prep_kernel<<<256, 256>>>(W1, W2, x, out);
    fc1_kernel<<<dim3(3, 392), 256>>>(x, b1);
    conv_kernel<<<dim3(48, 32), 256>>>(conv_w, conv_b);
    fc2_kernel<<<dim3(6, 392), 256>>>(x, b2, out);
}